// round 8
// baseline (speedup 1.0000x reference)
#include <cuda_runtime.h>
#include <cuda_bf16.h>
#include <cstdint>

#define B_  2
#define S_  2048
#define D_  1024
#define H_  16
#define HD_ 64
#define NELEM (B_*S_*D_)      // 4194304

// Scratch (allocation-free rule: __device__ globals)
__device__ __align__(16) float g_V[NELEM];                // [B,H,S,HD] fp32
__device__ __align__(16) __nv_bfloat16 g_xhi[NELEM];      // activations hi
__device__ __align__(16) __nv_bfloat16 g_xlo[NELEM];      // activations lo
__device__ __align__(16) __nv_bfloat16 g_whi[4*D_*D_];    // Wq,Wk,Wv,Wo hi
__device__ __align__(16) __nv_bfloat16 g_wlo[4*D_*D_];    // Wq,Wk,Wv,Wo lo
__device__ __align__(16) __nv_bfloat16 g_Qhi[NELEM];      // [B,H,S,HD] (scaled by 0.125*log2e)
__device__ __align__(16) __nv_bfloat16 g_Qlo[NELEM];
__device__ __align__(16) __nv_bfloat16 g_Khi[NELEM];      // [B,H,S,HD]
__device__ __align__(16) __nv_bfloat16 g_Klo[NELEM];
__device__ __align__(16) __nv_bfloat16 g_Vthi[NELEM];     // [B,H,HD,S] (transposed)
__device__ __align__(16) __nv_bfloat16 g_Vtlo[NELEM];
__device__ __align__(16) uint32_t g_mbits[B_*S_*(S_/32)]; // packed mask bits

// ===========================================================================
// PTX helpers (baseline PTX only — compiles under compute_103)
// ===========================================================================
__device__ __forceinline__ uint32_t smem_u32(const void* p) {
    uint32_t a;
    asm("{ .reg .u64 t; cvta.to.shared.u64 t, %1; cvt.u32.u64 %0, t; }"
        : "=r"(a) : "l"(p));
    return a;
}
__device__ __forceinline__ void cp16(uint32_t saddr, const void* g) {
    asm volatile("cp.async.cg.shared.global [%0], [%1], 16;"
                 :: "r"(saddr), "l"(g) : "memory");
}
__device__ __forceinline__ void ldm_x4(uint32_t* r, uint32_t addr) {
    asm volatile("ldmatrix.sync.aligned.m8n8.x4.shared.b16 {%0,%1,%2,%3}, [%4];"
        : "=r"(r[0]), "=r"(r[1]), "=r"(r[2]), "=r"(r[3]) : "r"(addr));
}
__device__ __forceinline__ void mma_bf16(float* c, const uint32_t* a, const uint32_t* b) {
    asm volatile("mma.sync.aligned.m16n8k16.row.col.f32.bf16.bf16.f32 "
        "{%0,%1,%2,%3}, {%4,%5,%6,%7}, {%8,%9}, {%0,%1,%2,%3};"
        : "+f"(c[0]), "+f"(c[1]), "+f"(c[2]), "+f"(c[3])
        : "r"(a[0]), "r"(a[1]), "r"(a[2]), "r"(a[3]), "r"(b[0]), "r"(b[1]));
}
__device__ __forceinline__ float ex2f(float x) {
    float r;
    asm("ex2.approx.f32 %0, %1;" : "=f"(r) : "f"(x));
    return r;
}

// Fast fp32 pair -> packed hi (truncated bf16) + packed lo (rounded remainder)
__device__ __forceinline__ void split2(float x, float y, uint32_t& h, uint32_t& l) {
    const uint32_t xb = __float_as_uint(x) & 0xFFFF0000u;
    const uint32_t yb = __float_as_uint(y) & 0xFFFF0000u;
    h = (xb >> 16) | yb;                       // {lo16=bf16(x), hi16=bf16(y)}
    const float lx = x - __uint_as_float(xb);  // exact
    const float ly = y - __uint_as_float(yb);  // exact
    asm("cvt.rn.bf16x2.f32 %0, %1, %2;" : "=r"(l) : "f"(ly), "f"(lx));
}

// ---------------------------------------------------------------------------
// split kernels
// ---------------------------------------------------------------------------
__global__ __launch_bounds__(256) void split_x_kernel(
    const float* __restrict__ src,
    __nv_bfloat16* __restrict__ hi, __nv_bfloat16* __restrict__ lo)
{
    const int i = (blockIdx.x * 256 + threadIdx.x) * 4;
    const float4 v = *(const float4*)(src + i);
    uint2 hv, lv;
    split2(v.x, v.y, hv.x, lv.x);
    split2(v.z, v.w, hv.y, lv.y);
    *(uint2*)(hi + i) = hv;
    *(uint2*)(lo + i) = lv;
}

__global__ __launch_bounds__(256) void split_w_kernel(
    const float* __restrict__ w0, const float* __restrict__ w1,
    const float* __restrict__ w2, const float* __restrict__ w3)
{
    const int wsel = blockIdx.y;
    const float* src = (wsel == 0) ? w0 : (wsel == 1) ? w1 : (wsel == 2) ? w2 : w3;
    const int i = (blockIdx.x * 256 + threadIdx.x) * 4;
    const float4 v = *(const float4*)(src + i);
    uint2 hv, lv;
    split2(v.x, v.y, hv.x, lv.x);
    split2(v.z, v.w, hv.y, lv.y);
    const size_t o = (size_t)wsel * D_ * D_ + i;
    *(uint2*)(g_whi + o) = hv;
    *(uint2*)(g_wlo + o) = lv;
}

// ---------------------------------------------------------------------------
// mask pack: bit j of word w of row (b,q) = (M[b,q,w*32+j] != 0)
// ---------------------------------------------------------------------------
__global__ __launch_bounds__(256) void packmask_kernel(const int* __restrict__ M)
{
    const int lane = threadIdx.x & 31;
    const int row = blockIdx.x * 8 + (threadIdx.x >> 5);   // 0..4095
    const int* src = M + (size_t)row * S_;
    uint32_t* dst = g_mbits + row * (S_/32);
    for (int w = 0; w < S_/32; w++) {
        const int v = src[w * 32 + lane];
        const uint32_t bits = __ballot_sync(0xffffffffu, v != 0);
        if (lane == 0) dst[w] = bits;
    }
}

// ---------------------------------------------------------------------------
// V transpose+split: g_V [B,H,S,64] fp32 -> g_Vthi/lo [B,H,64,S] bf16
// ---------------------------------------------------------------------------
__global__ __launch_bounds__(256) void vtrans_kernel()
{
    __shared__ float t[64][65];
    const int bh = blockIdx.y;
    const int k0 = blockIdx.x * 64;
    const float* src = g_V + ((size_t)bh * S_ + k0) * HD_;
    const int tid = threadIdx.x;
    #pragma unroll
    for (int it = 0; it < 4; it++) {
        const int r = (tid >> 4) + it * 16;
        const int c = (tid & 15) * 4;
        const float4 v = *(const float4*)(src + r * HD_ + c);
        t[r][c] = v.x; t[r][c+1] = v.y; t[r][c+2] = v.z; t[r][c+3] = v.w;
    }
    __syncthreads();
    #pragma unroll
    for (int it = 0; it < 4; it++) {
        const int d  = (tid >> 4) + it * 16;
        const int k4 = (tid & 15) * 4;
        uint32_t h0, l0, h1, l1;
        split2(t[k4][d],   t[k4+1][d], h0, l0);
        split2(t[k4+2][d], t[k4+3][d], h1, l1);
        const size_t o = ((size_t)bh * HD_ + d) * S_ + k0 + k4;
        *(uint2*)&g_Vthi[o] = make_uint2(h0, h1);
        *(uint2*)&g_Vtlo[o] = make_uint2(l0, l1);
    }
}

// ===========================================================================
// HMMA GEMM (unchanged from R7): C[m,n] = sum_k A[m,k]*W[n,k], 3-term bf16.
// ===========================================================================
#define KC 32
#define NCH 32
#define AP 40
#define TILE_ELT (128*AP)

template<int MODE>
__global__ __launch_bounds__(256, 2) void tgemm_kernel(
    const __nv_bfloat16* __restrict__ Ahi_g,
    const __nv_bfloat16* __restrict__ Alo_g,
    const float* __restrict__ bias,
    float* __restrict__ Cout)
{
    extern __shared__ __nv_bfloat16 smem[];
    const uint32_t sb = smem_u32(smem);

    const int tid = threadIdx.x;
    const int wid = tid >> 5, lane = tid & 31;
    const int m0 = blockIdx.y * 128;
    const int n0 = blockIdx.x * 128;
    const int widx = (MODE == 0) ? blockIdx.z : 3;
    const __nv_bfloat16* Bhi_g = g_whi + (size_t)widx * D_ * D_;
    const __nv_bfloat16* Blo_g = g_wlo + (size_t)widx * D_ * D_;

    const int lrow0 = tid >> 2;
    const int lcol  = (tid & 3) * 8;

    const int arow  = (lane & 7) + ((lane >> 3) & 1) * 8;
    const int akoff = ((lane >> 4) & 1) * 8;
    const int btile = lane >> 4;
    const int bk    = (lane >> 3) & 1;
    const int br    = lane & 7;
    const int wm = (wid & 1) * 64;
    const int wn = (wid >> 1) * 32;

    float acc[4][4][4];
    #pragma unroll
    for (int mt = 0; mt < 4; mt++)
        #pragma unroll
        for (int nt = 0; nt < 4; nt++)
            #pragma unroll
            for (int j = 0; j < 4; j++) acc[mt][nt][j] = 0.f;

    auto prefetch = [&](int c) {
        const int buf = c & 1;
        const int kc = c * KC;
        const uint32_t s0 = sb + (uint32_t)(buf * 4 * TILE_ELT) * 2;
        const uint32_t soff = (uint32_t)(lrow0 * AP + lcol) * 2;
        {
            const __nv_bfloat16* g = Ahi_g + (size_t)(m0 + lrow0) * 1024 + kc + lcol;
            cp16(s0 + 0 * TILE_ELT * 2 + soff, g);
            cp16(s0 + 0 * TILE_ELT * 2 + soff + 64 * AP * 2, g + 64 * 1024);
        }
        {
            const __nv_bfloat16* g = Alo_g + (size_t)(m0 + lrow0) * 1024 + kc + lcol;
            cp16(s0 + 1 * TILE_ELT * 2 + soff, g);
            cp16(s0 + 1 * TILE_ELT * 2 + soff + 64 * AP * 2, g + 64 * 1024);
        }
        {
            const __nv_bfloat16* g = Bhi_g + (size_t)(n0 + lrow0) * 1024 + kc + lcol;
            cp16(s0 + 2 * TILE_ELT * 2 + soff, g);
            cp16(s0 + 2 * TILE_ELT * 2 + soff + 64 * AP * 2, g + 64 * 1024);
        }
        {
            const __nv_bfloat16* g = Blo_g + (size_t)(n0 + lrow0) * 1024 + kc + lcol;
            cp16(s0 + 3 * TILE_ELT * 2 + soff, g);
            cp16(s0 + 3 * TILE_ELT * 2 + soff + 64 * AP * 2, g + 64 * 1024);
        }
        asm volatile("cp.async.commit_group;" ::: "memory");
    };

    prefetch(0);

    for (int c = 0; c < NCH; c++) {
        if (c + 1 < NCH) {
            prefetch(c + 1);
            asm volatile("cp.async.wait_group 1;" ::: "memory");
        } else {
            asm volatile("cp.async.wait_group 0;" ::: "memory");
        }
        __syncthreads();

        const int buf = c & 1;
        const uint32_t base = sb + (uint32_t)(buf * 4 * TILE_ELT) * 2;
        const uint32_t aAhi = base;
        const uint32_t aAlo = base + (uint32_t)TILE_ELT * 2;
        const uint32_t aBhi = base + (uint32_t)TILE_ELT * 4;
        const uint32_t aBlo = base + (uint32_t)TILE_ELT * 6;

        #pragma unroll
        for (int ks = 0; ks < 2; ks++) {
            const int k0 = ks * 16;
            uint32_t bh[4][2], bl[4][2];
            #pragma unroll
            for (int p = 0; p < 2; p++) {
                const uint32_t ba = (uint32_t)(
                    (wn + (p * 2 + btile) * 8 + br) * AP + k0 + bk * 8) * 2;
                ldm_x4(&bh[p*2][0], aBhi + ba);
                ldm_x4(&bl[p*2][0], aBlo + ba);
            }
            #pragma unroll
            for (int mt = 0; mt < 4; mt++) {
                const uint32_t aa =
                    (uint32_t)((wm + mt * 16 + arow) * AP + k0 + akoff) * 2;
                uint32_t ah[4], al[4];
                ldm_x4(ah, aAhi + aa);
                ldm_x4(al, aAlo + aa);
                #pragma unroll
                for (int nt = 0; nt < 4; nt++) mma_bf16(acc[mt][nt], ah, bh[nt]);
                #pragma unroll
                for (int nt = 0; nt < 4; nt++) mma_bf16(acc[mt][nt], ah, bl[nt]);
                #pragma unroll
                for (int nt = 0; nt < 4; nt++) mma_bf16(acc[mt][nt], al, bh[nt]);
            }
        }
        __syncthreads();
    }

    // ---- epilogue ----
    const int r_lo  = lane >> 2;
    const int coff  = (lane & 3) * 2;
    const float scale = (MODE == 0 && blockIdx.z == 0) ? 0.125f * 1.44269504f : 1.0f;

    #pragma unroll
    for (int mt = 0; mt < 4; mt++) {
        const int r0 = m0 + wm + mt * 16 + r_lo;
        const int r1 = r0 + 8;
        #pragma unroll
        for (int nt = 0; nt < 4; nt++) {
            const int cg = n0 + wn + nt * 8 + coff;
            float2 v0 = make_float2(acc[mt][nt][0] * scale, acc[mt][nt][1] * scale);
            float2 v1 = make_float2(acc[mt][nt][2] * scale, acc[mt][nt][3] * scale);
            if (MODE == 0) {
                const int h = cg >> 6, hd = cg & 63;
                #pragma unroll
                for (int half = 0; half < 2; half++) {
                    const int rr = half ? r1 : r0;
                    const float2 v = half ? v1 : v0;
                    const int bb_ = rr >> 11, ss = rr & 2047;
                    const size_t o = (((size_t)(bb_ * H_ + h)) * S_ + ss) * HD_ + hd;
                    if (blockIdx.z == 2) {
                        *(float2*)&g_V[o] = v;
                    } else {
                        uint32_t hw, lw;
                        split2(v.x, v.y, hw, lw);
                        if (blockIdx.z == 0) {
                            *(uint32_t*)&g_Qhi[o] = hw;
                            *(uint32_t*)&g_Qlo[o] = lw;
                        } else {
                            *(uint32_t*)&g_Khi[o] = hw;
                            *(uint32_t*)&g_Klo[o] = lw;
                        }
                    }
                }
            } else {
                const float2 bb = *(const float2*)&bias[cg];
                v0.x += bb.x; v0.y += bb.y;
                v1.x += bb.x; v1.y += bb.y;
                *(float2*)&Cout[(size_t)r0 * 1024 + cg] = v0;
                *(float2*)&Cout[(size_t)r1 * 1024 + cg] = v1;
            }
        }
    }
}

// ===========================================================================
// Tensor-core flash attention — software-pipelined.
// 256 threads / 128 queries per CTA (8 warps, warp = 16 q rows).
// 3-stage KV smem (prefetch depth 2). Q fragments cached in registers.
// Loop body interleaves QK(c+1) with PV(c); softmax(c+1) runs after the
// barrier so warps drift through it while others issue MMAs.
// ===========================================================================
#define QP 72
#define QROWS 128
#define QSZ (QROWS*QP)
#define CHE (64*QP)

__global__ __launch_bounds__(256) void attn_tc()
{
    extern __shared__ __nv_bfloat16 sm[];
    const uint32_t sb = smem_u32(sm);
    const int tid = threadIdx.x, wid = tid >> 5, lane = tid & 31;
    const int bh = blockIdx.y, b = bh >> 4, h = bh & 15;
    const int q0 = blockIdx.x * QROWS;

    const __nv_bfloat16* Qhi_g = g_Qhi + ((size_t)bh * S_ + q0) * HD_;
    const __nv_bfloat16* Qlo_g = g_Qlo + ((size_t)bh * S_ + q0) * HD_;
    const __nv_bfloat16* Khi_g = g_Khi + (size_t)bh * S_ * HD_;
    const __nv_bfloat16* Klo_g = g_Klo + (size_t)bh * S_ * HD_;
    const __nv_bfloat16* Vhi_g = g_Vthi + (size_t)bh * HD_ * S_;
    const __nv_bfloat16* Vlo_g = g_Vtlo + (size_t)bh * HD_ * S_;

    // Q tiles (hi, lo) -> smem once; joins cp.async group 0
    #pragma unroll
    for (int t = 0; t < 8; t++) {
        const int i = tid + t * 256;                 // 0..2047
        const int mat = i >> 10, rem = i & 1023, row = rem >> 3, c16 = rem & 7;
        const __nv_bfloat16* g = (mat ? Qlo_g : Qhi_g) + row * HD_ + c16 * 8;
        cp16(sb + (uint32_t)(mat * QSZ + row * QP) * 2 + c16 * 16, g);
    }

    auto prefetch = [&](int c) {
        const int stage = c % 3;
        const int k0 = c * 64;
        const uint32_t base = (uint32_t)(2 * QSZ + stage * 4 * CHE);
        #pragma unroll
        for (int t = 0; t < 8; t++) {
            const int i = tid + t * 256;             // 0..2047
            const int mat = i >> 9, rem = i & 511, row = rem >> 3, c16 = rem & 7;
            const __nv_bfloat16* g;
            if (mat == 0)      g = Khi_g + (size_t)(k0 + row) * HD_ + c16 * 8;
            else if (mat == 1) g = Klo_g + (size_t)(k0 + row) * HD_ + c16 * 8;
            else if (mat == 2) g = Vhi_g + (size_t)row * S_ + k0 + c16 * 8;
            else               g = Vlo_g + (size_t)row * S_ + k0 + c16 * 8;
            cp16(sb + (base + (uint32_t)(mat * CHE + row * QP)) * 2 + c16 * 16, g);
        }
        asm volatile("cp.async.commit_group;" ::: "memory");
    };

    prefetch(0);   // group 0 (includes Q)
    prefetch(1);   // group 1

    const int arow  = (lane & 7) + ((lane >> 3) & 1) * 8;
    const int akoff = ((lane >> 4) & 1) * 8;
    const int btile = lane >> 4;
    const int bk    = (lane >> 3) & 1;
    const int br    = lane & 7;
    const int r = lane >> 2;

    float out[8][4];
    #pragma unroll
    for (int nt = 0; nt < 8; nt++)
        #pragma unroll
        for (int j = 0; j < 4; j++) out[nt][j] = 0.f;
    float m0 = -1e30f, m1 = -1e30f, l0 = 0.f, l1 = 0.f;
    float s[8][4];     // P values of current chunk (post-softmax)

    const uint32_t mrow0 = ((uint32_t)b * S_ + q0 + wid * 16 + r) * (S_/32);

    asm volatile("cp.async.wait_group 1;" ::: "memory");   // group 0 done
    __syncthreads();

    // cache Q fragments in registers (4 k-steps x hi/lo)
    uint32_t qfh[4][4], qfl[4][4];
    #pragma unroll
    for (int ks = 0; ks < 4; ks++) {
        const uint32_t qa = (uint32_t)((wid * 16 + arow) * QP + ks * 16 + akoff) * 2;
        ldm_x4(qfh[ks], sb + qa);
        ldm_x4(qfl[ks], sb + (uint32_t)QSZ * 2 + qa);
    }

    // ---- softmax helper applied to raw scores src (chunk cc); writes P into s,
    //      updates m/l and rescales out. ----
    auto softmax_chunk = [&](float (&src)[8][4], int cc) {
        const uint32_t widx = (uint32_t)(cc * 2);
        const uint2 mw0 = *(const uint2*)(g_mbits + mrow0 + widx);
        const uint2 mw1 = *(const uint2*)(g_mbits + mrow0 + 8 * (S_/32) + widx);
        #pragma unroll
        for (int nt = 0; nt < 8; nt++) {
            const int sh = ((nt * 8) & 31) + (lane & 3) * 2;
            const uint32_t w0 = (nt < 4) ? mw0.x : mw0.y;
            const uint32_t w1 = (nt < 4) ? mw1.x : mw1.y;
            if (!((w0 >> sh) & 1))       src[nt][0] = -1e9f;
            if (!((w0 >> (sh + 1)) & 1)) src[nt][1] = -1e9f;
            if (!((w1 >> sh) & 1))       src[nt][2] = -1e9f;
            if (!((w1 >> (sh + 1)) & 1)) src[nt][3] = -1e9f;
        }
        float mx0 = -1e30f, mx1 = -1e30f;
        #pragma unroll
        for (int nt = 0; nt < 8; nt++) {
            mx0 = fmaxf(mx0, fmaxf(src[nt][0], src[nt][1]));
            mx1 = fmaxf(mx1, fmaxf(src[nt][2], src[nt][3]));
        }
        mx0 = fmaxf(mx0, __shfl_xor_sync(0xffffffffu, mx0, 1));
        mx0 = fmaxf(mx0, __shfl_xor_sync(0xffffffffu, mx0, 2));
        mx1 = fmaxf(mx1, __shfl_xor_sync(0xffffffffu, mx1, 1));
        mx1 = fmaxf(mx1, __shfl_xor_sync(0xffffffffu, mx1, 2));
        const float mn0 = fmaxf(m0, mx0);
        const float mn1 = fmaxf(m1, mx1);
        const float a0 = ex2f(m0 - mn0);
        const float a1 = ex2f(m1 - mn1);
        m0 = mn0; m1 = mn1;
        float s0 = 0.f, s1 = 0.f;
        #pragma unroll
        for (int nt = 0; nt < 8; nt++) {
            s[nt][0] = ex2f(src[nt][0] - mn0); s0 += s[nt][0];
            s[nt][1] = ex2f(src[nt][1] - mn0); s0 += s[nt][1];
            s[nt][2] = ex2f(src[nt][2] - mn1); s1 += s[nt][2];
            s[nt][3] = ex2f(src[nt][3] - mn1); s1 += s[nt][3];
        }
        s0 += __shfl_xor_sync(0xffffffffu, s0, 1);
        s0 += __shfl_xor_sync(0xffffffffu, s0, 2);
        s1 += __shfl_xor_sync(0xffffffffu, s1, 1);
        s1 += __shfl_xor_sync(0xffffffffu, s1, 2);
        l0 = l0 * a0 + s0;
        l1 = l1 * a1 + s1;
        #pragma unroll
        for (int nt = 0; nt < 8; nt++) {
            out[nt][0] *= a0; out[nt][1] *= a0;
            out[nt][2] *= a1; out[nt][3] *= a1;
        }
    };

    // ---- chunk 0: QK only, then softmax ----
    {
        const uint32_t kb = sb + (uint32_t)(2 * QSZ + 0 * 4 * CHE) * 2;
        float sn[8][4];
        #pragma unroll
        for (int nt = 0; nt < 8; nt++)
            #pragma unroll
            for (int j = 0; j < 4; j++) sn[nt][j] = 0.f;
        #pragma unroll
        for (int ks = 0; ks < 4; ks++) {
            #pragma unroll
            for (int half = 0; half < 2; half++) {
                uint32_t kh[4][2], kl[4][2];
                #pragma unroll
                for (int p = 0; p < 2; p++) {
                    const int t0 = half * 4 + p * 2;
                    const uint32_t ka = kb + (uint32_t)(
                        ((t0 + btile) * 8 + br) * QP + ks * 16 + bk * 8) * 2;
                    ldm_x4(&kh[p*2][0], ka);
                    ldm_x4(&kl[p*2][0], ka + (uint32_t)CHE * 2);
                }
                #pragma unroll
                for (int q = 0; q < 4; q++) mma_bf16(sn[half*4+q], qfh[ks], kh[q]);
                #pragma unroll
                for (int q = 0; q < 4; q++) mma_bf16(sn[half*4+q], qfh[ks], kl[q]);
                #pragma unroll
                for (int q = 0; q < 4; q++) mma_bf16(sn[half*4+q], qfl[ks], kh[q]);
            }
        }
        softmax_chunk(sn, 0);
    }

    // ---- main pipelined loop: iteration c does QK(c+1) + PV(c), then softmax(c+1)
    for (int c = 0; c < 31; c++) {
        if (c < 30) {
            prefetch(c + 2);
            asm volatile("cp.async.wait_group 1;" ::: "memory");   // group c+1 done
        } else {
            asm volatile("cp.async.wait_group 0;" ::: "memory");   // group 31 done
        }

        const uint32_t kbQ = sb + (uint32_t)(2 * QSZ + ((c + 1) % 3) * 4 * CHE) * 2;
        const uint32_t kbP = sb + (uint32_t)(2 * QSZ + (c % 3) * 4 * CHE) * 2;

        float sn[8][4];
        #pragma unroll
        for (int nt = 0; nt < 8; nt++)
            #pragma unroll
            for (int j = 0; j < 4; j++) sn[nt][j] = 0.f;

        #pragma unroll
        for (int j = 0; j < 4; j++) {
            uint32_t ah[4], al[4];
            split2(s[2*j][0],   s[2*j][1],   ah[0], al[0]);
            split2(s[2*j][2],   s[2*j][3],   ah[1], al[1]);
            split2(s[2*j+1][0], s[2*j+1][1], ah[2], al[2]);
            split2(s[2*j+1][2], s[2*j+1][3], ah[3], al[3]);
            #pragma unroll
            for (int half = 0; half < 2; half++) {
                uint32_t kh[4][2], kl[4][2], vh[4][2], vl[4][2];
                #pragma unroll
                for (int p = 0; p < 2; p++) {
                    const int t0 = half * 4 + p * 2;
                    const uint32_t ka = kbQ + (uint32_t)(
                        ((t0 + btile) * 8 + br) * QP + j * 16 + bk * 8) * 2;
                    ldm_x4(&kh[p*2][0], ka);
                    ldm_x4(&kl[p*2][0], ka + (uint32_t)CHE * 2);
                    const uint32_t va = kbP + (uint32_t)(
                        2 * CHE + ((t0 + btile) * 8 + br) * QP + j * 16 + bk * 8) * 2;
                    ldm_x4(&vh[p*2][0], va);
                    ldm_x4(&vl[p*2][0], va + (uint32_t)CHE * 2);
                }
                // interleaved QK / PV groups of 4 (RAW distance 8)
                #pragma unroll
                for (int q = 0; q < 4; q++) mma_bf16(sn[half*4+q], qfh[j], kh[q]);
                #pragma unroll
                for (int q = 0; q < 4; q++) mma_bf16(out[half*4+q], ah, vh[q]);
                #pragma unroll
                for (int q = 0; q < 4; q++) mma_bf16(sn[half*4+q], qfh[j], kl[q]);
                #pragma unroll
                for (int q = 0; q < 4; q++) mma_bf16(out[half*4+q], ah, vl[q]);
                #pragma unroll
                for (int q = 0; q < 4; q++) mma_bf16(sn[half*4+q], qfl[j], kh[q]);
                #pragma unroll
                for (int q = 0; q < 4; q++) mma_bf16(out[half*4+q], al, vh[q]);
            }
        }
        __syncthreads();    // protects stage (c%3) reuse by prefetch(c+3) next iter
        softmax_chunk(sn, c + 1);
    }

    // ---- final PV for chunk 31 (stage 31%3 = 2) ----
    {
        const uint32_t kbP = sb + (uint32_t)(2 * QSZ + (31 % 3) * 4 * CHE) * 2;
        #pragma unroll
        for (int j = 0; j < 4; j++) {
            uint32_t ah[4], al[4];
            split2(s[2*j][0],   s[2*j][1],   ah[0], al[0]);
            split2(s[2*j][2],   s[2*j][3],   ah[1], al[1]);
            split2(s[2*j+1][0], s[2*j+1][1], ah[2], al[2]);
            split2(s[2*j+1][2], s[2*j+1][3], ah[3], al[3]);
            #pragma unroll
            for (int half = 0; half < 2; half++) {
                uint32_t vh[4][2], vl[4][2];
                #pragma unroll
                for (int p = 0; p < 2; p++) {
                    const int t0 = half * 4 + p * 2;
                    const uint32_t va = kbP + (uint32_t)(
                        2 * CHE + ((t0 + btile) * 8 + br) * QP + j * 16 + bk * 8) * 2;
                    ldm_x4(&vh[p*2][0], va);
                    ldm_x4(&vl[p*2][0], va + (uint32_t)CHE * 2);
                }
                #pragma unroll
                for (int q = 0; q < 4; q++) mma_bf16(out[half*4+q], ah, vh[q]);
                #pragma unroll
                for (int q = 0; q < 4; q++) mma_bf16(out[half*4+q], ah, vl[q]);
                #pragma unroll
                for (int q = 0; q < 4; q++) mma_bf16(out[half*4+q], al, vh[q]);
            }
        }
    }

    // ---- epilogue: normalize, split, store bf16 hi/lo into g_xhi/g_xlo ----
    const float i0 = 1.0f / l0;
    const float i1 = 1.0f / l1;
    const int qg = q0 + wid * 16 + r;
    #pragma unroll
    for (int nt = 0; nt < 8; nt++) {
        const int d = nt * 8 + (lane & 3) * 2;
        const size_t o0 = ((size_t)b * S_ + qg) * D_ + h * HD_ + d;
        const size_t o1 = o0 + 8 * D_;
        uint32_t hw, lw;
        split2(out[nt][0] * i0, out[nt][1] * i0, hw, lw);
        *(uint32_t*)&g_xhi[o0] = hw;
        *(uint32_t*)&g_xlo[o0] = lw;
        split2(out[nt][2] * i1, out[nt][3] * i1, hw, lw);
        *(uint32_t*)&g_xhi[o1] = hw;
        *(uint32_t*)&g_xlo[o1] = lw;
    }
}

// ---------------------------------------------------------------------------
extern "C" void kernel_launch(void* const* d_in, const int* in_sizes, int n_in,
                              void* d_out, int out_size)
{
    const float* x  = (const float*)d_in[0];
    const int*   Mm = (const int*)  d_in[1];
    const float* Wq = (const float*)d_in[2];
    const float* Wk = (const float*)d_in[3];
    const float* Wv = (const float*)d_in[4];
    const float* Wo = (const float*)d_in[5];
    const float* bo = (const float*)d_in[6];
    float* out = (float*)d_out;

    __nv_bfloat16 *xhiPtr = nullptr, *xloPtr = nullptr;
    cudaGetSymbolAddress((void**)&xhiPtr, g_xhi);
    cudaGetSymbolAddress((void**)&xloPtr, g_xlo);

    const int gemm_smem = 2 * 4 * TILE_ELT * 2;             // 81920 B
    cudaFuncSetAttribute(tgemm_kernel<0>,
                         cudaFuncAttributeMaxDynamicSharedMemorySize, gemm_smem);
    cudaFuncSetAttribute(tgemm_kernel<1>,
                         cudaFuncAttributeMaxDynamicSharedMemorySize, gemm_smem);
    const int attn_smem = (2 * QSZ + 12 * CHE) * 2;         // 147456 B
    cudaFuncSetAttribute(attn_tc,
                         cudaFuncAttributeMaxDynamicSharedMemorySize, attn_smem);

    // 1) split input x and all weights to hi/lo bf16
    split_x_kernel<<<NELEM/1024, 256>>>(x, xhiPtr, xloPtr);
    split_w_kernel<<<dim3((D_*D_)/1024, 4), 256>>>(Wq, Wk, Wv, Wo);
    // 2) QKV projections (HMMA); epilogue splits Q/K to bf16, V stays fp32
    tgemm_kernel<0><<<dim3(8, 32, 3), 256, gemm_smem>>>(xhiPtr, xloPtr, nullptr, nullptr);
    // 3) pack mask bits; transpose+split V
    packmask_kernel<<<(B_*S_)/8, 256>>>(Mm);
    vtrans_kernel<<<dim3(S_/64, B_*H_), 256>>>();
    // 4) pipelined tensor-core flash attention -> g_xhi/g_xlo [B,S,D]
    attn_tc<<<dim3(S_/QROWS, B_*H_), 256, attn_smem>>>();
    // 5) output projection + bias (HMMA)
    tgemm_kernel<1><<<dim3(8, 32, 1), 256, gemm_smem>>>(xhiPtr, xloPtr, bo, out);
}

// round 9
// speedup vs baseline: 1.0844x; 1.0844x over previous
#include <cuda_runtime.h>
#include <cuda_bf16.h>
#include <cstdint>

#define B_  2
#define S_  2048
#define D_  1024
#define H_  16
#define HD_ 64
#define NELEM (B_*S_*D_)      // 4194304

// Scratch (allocation-free rule: __device__ globals)
__device__ __align__(16) float g_V[NELEM];                // [B,H,S,HD] fp32
__device__ __align__(16) __nv_bfloat16 g_xhi[NELEM];      // activations hi
__device__ __align__(16) __nv_bfloat16 g_xlo[NELEM];      // activations lo
__device__ __align__(16) __nv_bfloat16 g_whi[4*D_*D_];    // Wq,Wk,Wv,Wo hi
__device__ __align__(16) __nv_bfloat16 g_wlo[4*D_*D_];    // Wq,Wk,Wv,Wo lo
__device__ __align__(16) __nv_bfloat16 g_Qhi[NELEM];      // [B,H,S,HD] (scaled by 0.125*log2e)
__device__ __align__(16) __nv_bfloat16 g_Qlo[NELEM];
__device__ __align__(16) __nv_bfloat16 g_Khi[NELEM];      // [B,H,S,HD]
__device__ __align__(16) __nv_bfloat16 g_Klo[NELEM];
__device__ __align__(16) __nv_bfloat16 g_Vthi[NELEM];     // [B,H,HD,S] (transposed)
__device__ __align__(16) __nv_bfloat16 g_Vtlo[NELEM];
__device__ __align__(16) uint32_t g_mbits[B_*S_*(S_/32)]; // packed mask bits

// ===========================================================================
// PTX helpers (baseline PTX only — compiles under compute_103)
// ===========================================================================
__device__ __forceinline__ uint32_t smem_u32(const void* p) {
    uint32_t a;
    asm("{ .reg .u64 t; cvta.to.shared.u64 t, %1; cvt.u32.u64 %0, t; }"
        : "=r"(a) : "l"(p));
    return a;
}
__device__ __forceinline__ void cp16(uint32_t saddr, const void* g) {
    asm volatile("cp.async.cg.shared.global [%0], [%1], 16;"
                 :: "r"(saddr), "l"(g) : "memory");
}
__device__ __forceinline__ void ldm_x4(uint32_t* r, uint32_t addr) {
    asm volatile("ldmatrix.sync.aligned.m8n8.x4.shared.b16 {%0,%1,%2,%3}, [%4];"
        : "=r"(r[0]), "=r"(r[1]), "=r"(r[2]), "=r"(r[3]) : "r"(addr));
}
__device__ __forceinline__ void mma_bf16(float* c, const uint32_t* a, const uint32_t* b) {
    asm volatile("mma.sync.aligned.m16n8k16.row.col.f32.bf16.bf16.f32 "
        "{%0,%1,%2,%3}, {%4,%5,%6,%7}, {%8,%9}, {%0,%1,%2,%3};"
        : "+f"(c[0]), "+f"(c[1]), "+f"(c[2]), "+f"(c[3])
        : "r"(a[0]), "r"(a[1]), "r"(a[2]), "r"(a[3]), "r"(b[0]), "r"(b[1]));
}
__device__ __forceinline__ float ex2f(float x) {
    float r;
    asm("ex2.approx.f32 %0, %1;" : "=f"(r) : "f"(x));
    return r;
}

// Fast fp32 pair -> packed hi (truncated bf16) + packed lo (rounded remainder)
__device__ __forceinline__ void split2(float x, float y, uint32_t& h, uint32_t& l) {
    const uint32_t xb = __float_as_uint(x) & 0xFFFF0000u;
    const uint32_t yb = __float_as_uint(y) & 0xFFFF0000u;
    h = (xb >> 16) | yb;                       // {lo16=bf16(x), hi16=bf16(y)}
    const float lx = x - __uint_as_float(xb);  // exact
    const float ly = y - __uint_as_float(yb);  // exact
    asm("cvt.rn.bf16x2.f32 %0, %1, %2;" : "=r"(l) : "f"(ly), "f"(lx));
}

// ---------------------------------------------------------------------------
// split kernels
// ---------------------------------------------------------------------------
__global__ __launch_bounds__(256) void split_x_kernel(
    const float* __restrict__ src,
    __nv_bfloat16* __restrict__ hi, __nv_bfloat16* __restrict__ lo)
{
    const int i = (blockIdx.x * 256 + threadIdx.x) * 4;
    const float4 v = *(const float4*)(src + i);
    uint2 hv, lv;
    split2(v.x, v.y, hv.x, lv.x);
    split2(v.z, v.w, hv.y, lv.y);
    *(uint2*)(hi + i) = hv;
    *(uint2*)(lo + i) = lv;
}

__global__ __launch_bounds__(256) void split_w_kernel(
    const float* __restrict__ w0, const float* __restrict__ w1,
    const float* __restrict__ w2, const float* __restrict__ w3)
{
    const int wsel = blockIdx.y;
    const float* src = (wsel == 0) ? w0 : (wsel == 1) ? w1 : (wsel == 2) ? w2 : w3;
    const int i = (blockIdx.x * 256 + threadIdx.x) * 4;
    const float4 v = *(const float4*)(src + i);
    uint2 hv, lv;
    split2(v.x, v.y, hv.x, lv.x);
    split2(v.z, v.w, hv.y, lv.y);
    const size_t o = (size_t)wsel * D_ * D_ + i;
    *(uint2*)(g_whi + o) = hv;
    *(uint2*)(g_wlo + o) = lv;
}

// ---------------------------------------------------------------------------
// mask pack: bit j of word w of row (b,q) = (M[b,q,w*32+j] != 0)
// ---------------------------------------------------------------------------
__global__ __launch_bounds__(256) void packmask_kernel(const int* __restrict__ M)
{
    const int lane = threadIdx.x & 31;
    const int row = blockIdx.x * 8 + (threadIdx.x >> 5);   // 0..4095
    const int* src = M + (size_t)row * S_;
    uint32_t* dst = g_mbits + row * (S_/32);
    for (int w = 0; w < S_/32; w++) {
        const int v = src[w * 32 + lane];
        const uint32_t bits = __ballot_sync(0xffffffffu, v != 0);
        if (lane == 0) dst[w] = bits;
    }
}

// ---------------------------------------------------------------------------
// V transpose+split: g_V [B,H,S,64] fp32 -> g_Vthi/lo [B,H,64,S] bf16
// ---------------------------------------------------------------------------
__global__ __launch_bounds__(256) void vtrans_kernel()
{
    __shared__ float t[64][65];
    const int bh = blockIdx.y;
    const int k0 = blockIdx.x * 64;
    const float* src = g_V + ((size_t)bh * S_ + k0) * HD_;
    const int tid = threadIdx.x;
    #pragma unroll
    for (int it = 0; it < 4; it++) {
        const int r = (tid >> 4) + it * 16;
        const int c = (tid & 15) * 4;
        const float4 v = *(const float4*)(src + r * HD_ + c);
        t[r][c] = v.x; t[r][c+1] = v.y; t[r][c+2] = v.z; t[r][c+3] = v.w;
    }
    __syncthreads();
    #pragma unroll
    for (int it = 0; it < 4; it++) {
        const int d  = (tid >> 4) + it * 16;
        const int k4 = (tid & 15) * 4;
        uint32_t h0, l0, h1, l1;
        split2(t[k4][d],   t[k4+1][d], h0, l0);
        split2(t[k4+2][d], t[k4+3][d], h1, l1);
        const size_t o = ((size_t)bh * HD_ + d) * S_ + k0 + k4;
        *(uint2*)&g_Vthi[o] = make_uint2(h0, h1);
        *(uint2*)&g_Vtlo[o] = make_uint2(l0, l1);
    }
}

// ===========================================================================
// HMMA GEMM (unchanged, validated): C[m,n] = sum_k A[m,k]*W[n,k], 3-term bf16.
// ===========================================================================
#define KC 32
#define NCH 32
#define AP 40
#define TILE_ELT (128*AP)

template<int MODE>
__global__ __launch_bounds__(256, 2) void tgemm_kernel(
    const __nv_bfloat16* __restrict__ Ahi_g,
    const __nv_bfloat16* __restrict__ Alo_g,
    const float* __restrict__ bias,
    float* __restrict__ Cout)
{
    extern __shared__ __nv_bfloat16 smem[];
    const uint32_t sb = smem_u32(smem);

    const int tid = threadIdx.x;
    const int wid = tid >> 5, lane = tid & 31;
    const int m0 = blockIdx.y * 128;
    const int n0 = blockIdx.x * 128;
    const int widx = (MODE == 0) ? blockIdx.z : 3;
    const __nv_bfloat16* Bhi_g = g_whi + (size_t)widx * D_ * D_;
    const __nv_bfloat16* Blo_g = g_wlo + (size_t)widx * D_ * D_;

    const int lrow0 = tid >> 2;
    const int lcol  = (tid & 3) * 8;

    const int arow  = (lane & 7) + ((lane >> 3) & 1) * 8;
    const int akoff = ((lane >> 4) & 1) * 8;
    const int btile = lane >> 4;
    const int bk    = (lane >> 3) & 1;
    const int br    = lane & 7;
    const int wm = (wid & 1) * 64;
    const int wn = (wid >> 1) * 32;

    float acc[4][4][4];
    #pragma unroll
    for (int mt = 0; mt < 4; mt++)
        #pragma unroll
        for (int nt = 0; nt < 4; nt++)
            #pragma unroll
            for (int j = 0; j < 4; j++) acc[mt][nt][j] = 0.f;

    auto prefetch = [&](int c) {
        const int buf = c & 1;
        const int kc = c * KC;
        const uint32_t s0 = sb + (uint32_t)(buf * 4 * TILE_ELT) * 2;
        const uint32_t soff = (uint32_t)(lrow0 * AP + lcol) * 2;
        {
            const __nv_bfloat16* g = Ahi_g + (size_t)(m0 + lrow0) * 1024 + kc + lcol;
            cp16(s0 + 0 * TILE_ELT * 2 + soff, g);
            cp16(s0 + 0 * TILE_ELT * 2 + soff + 64 * AP * 2, g + 64 * 1024);
        }
        {
            const __nv_bfloat16* g = Alo_g + (size_t)(m0 + lrow0) * 1024 + kc + lcol;
            cp16(s0 + 1 * TILE_ELT * 2 + soff, g);
            cp16(s0 + 1 * TILE_ELT * 2 + soff + 64 * AP * 2, g + 64 * 1024);
        }
        {
            const __nv_bfloat16* g = Bhi_g + (size_t)(n0 + lrow0) * 1024 + kc + lcol;
            cp16(s0 + 2 * TILE_ELT * 2 + soff, g);
            cp16(s0 + 2 * TILE_ELT * 2 + soff + 64 * AP * 2, g + 64 * 1024);
        }
        {
            const __nv_bfloat16* g = Blo_g + (size_t)(n0 + lrow0) * 1024 + kc + lcol;
            cp16(s0 + 3 * TILE_ELT * 2 + soff, g);
            cp16(s0 + 3 * TILE_ELT * 2 + soff + 64 * AP * 2, g + 64 * 1024);
        }
        asm volatile("cp.async.commit_group;" ::: "memory");
    };

    prefetch(0);

    for (int c = 0; c < NCH; c++) {
        if (c + 1 < NCH) {
            prefetch(c + 1);
            asm volatile("cp.async.wait_group 1;" ::: "memory");
        } else {
            asm volatile("cp.async.wait_group 0;" ::: "memory");
        }
        __syncthreads();

        const int buf = c & 1;
        const uint32_t base = sb + (uint32_t)(buf * 4 * TILE_ELT) * 2;
        const uint32_t aAhi = base;
        const uint32_t aAlo = base + (uint32_t)TILE_ELT * 2;
        const uint32_t aBhi = base + (uint32_t)TILE_ELT * 4;
        const uint32_t aBlo = base + (uint32_t)TILE_ELT * 6;

        #pragma unroll
        for (int ks = 0; ks < 2; ks++) {
            const int k0 = ks * 16;
            uint32_t bh[4][2], bl[4][2];
            #pragma unroll
            for (int p = 0; p < 2; p++) {
                const uint32_t ba = (uint32_t)(
                    (wn + (p * 2 + btile) * 8 + br) * AP + k0 + bk * 8) * 2;
                ldm_x4(&bh[p*2][0], aBhi + ba);
                ldm_x4(&bl[p*2][0], aBlo + ba);
            }
            #pragma unroll
            for (int mt = 0; mt < 4; mt++) {
                const uint32_t aa =
                    (uint32_t)((wm + mt * 16 + arow) * AP + k0 + akoff) * 2;
                uint32_t ah[4], al[4];
                ldm_x4(ah, aAhi + aa);
                ldm_x4(al, aAlo + aa);
                #pragma unroll
                for (int nt = 0; nt < 4; nt++) mma_bf16(acc[mt][nt], ah, bh[nt]);
                #pragma unroll
                for (int nt = 0; nt < 4; nt++) mma_bf16(acc[mt][nt], ah, bl[nt]);
                #pragma unroll
                for (int nt = 0; nt < 4; nt++) mma_bf16(acc[mt][nt], al, bh[nt]);
            }
        }
        __syncthreads();
    }

    // ---- epilogue ----
    const int r_lo  = lane >> 2;
    const int coff  = (lane & 3) * 2;
    const float scale = (MODE == 0 && blockIdx.z == 0) ? 0.125f * 1.44269504f : 1.0f;

    #pragma unroll
    for (int mt = 0; mt < 4; mt++) {
        const int r0 = m0 + wm + mt * 16 + r_lo;
        const int r1 = r0 + 8;
        #pragma unroll
        for (int nt = 0; nt < 4; nt++) {
            const int cg = n0 + wn + nt * 8 + coff;
            float2 v0 = make_float2(acc[mt][nt][0] * scale, acc[mt][nt][1] * scale);
            float2 v1 = make_float2(acc[mt][nt][2] * scale, acc[mt][nt][3] * scale);
            if (MODE == 0) {
                const int h = cg >> 6, hd = cg & 63;
                #pragma unroll
                for (int half = 0; half < 2; half++) {
                    const int rr = half ? r1 : r0;
                    const float2 v = half ? v1 : v0;
                    const int bb_ = rr >> 11, ss = rr & 2047;
                    const size_t o = (((size_t)(bb_ * H_ + h)) * S_ + ss) * HD_ + hd;
                    if (blockIdx.z == 2) {
                        *(float2*)&g_V[o] = v;
                    } else {
                        uint32_t hw, lw;
                        split2(v.x, v.y, hw, lw);
                        if (blockIdx.z == 0) {
                            *(uint32_t*)&g_Qhi[o] = hw;
                            *(uint32_t*)&g_Qlo[o] = lw;
                        } else {
                            *(uint32_t*)&g_Khi[o] = hw;
                            *(uint32_t*)&g_Klo[o] = lw;
                        }
                    }
                }
            } else {
                const float2 bb = *(const float2*)&bias[cg];
                v0.x += bb.x; v0.y += bb.y;
                v1.x += bb.x; v1.y += bb.y;
                *(float2*)&Cout[(size_t)r0 * 1024 + cg] = v0;
                *(float2*)&Cout[(size_t)r1 * 1024 + cg] = v1;
            }
        }
    }
}

// ===========================================================================
// Tensor-core flash attention — pipelined, R7 occupancy (512 thr, QROWS 256).
// Loop: PV(c) -> wait -> barrier -> QK(c+1) -> prefetch(c+2) -> softmax(c+1).
// Softmax is in-place on the score array (out+p only: ~110 regs, no spill).
// Barrier sits between cross-thread cp.async completion and its readers, and
// between PV(c) reads and the stage-c overwrite by prefetch(c+2).
// ===========================================================================
#define QP 72
#define QROWS 256
#define QSZ (QROWS*QP)
#define CHE (64*QP)

__global__ __launch_bounds__(512) void attn_tc()
{
    extern __shared__ __nv_bfloat16 sm[];
    const uint32_t sb = smem_u32(sm);
    const int tid = threadIdx.x, wid = tid >> 5, lane = tid & 31;
    const int bh = blockIdx.y, b = bh >> 4, h = bh & 15;
    const int q0 = blockIdx.x * QROWS;

    const __nv_bfloat16* Qhi_g = g_Qhi + ((size_t)bh * S_ + q0) * HD_;
    const __nv_bfloat16* Qlo_g = g_Qlo + ((size_t)bh * S_ + q0) * HD_;
    const __nv_bfloat16* Khi_g = g_Khi + (size_t)bh * S_ * HD_;
    const __nv_bfloat16* Klo_g = g_Klo + (size_t)bh * S_ * HD_;
    const __nv_bfloat16* Vhi_g = g_Vthi + (size_t)bh * HD_ * S_;
    const __nv_bfloat16* Vlo_g = g_Vtlo + (size_t)bh * HD_ * S_;

    // Q tiles (hi, lo) -> smem once; joins cp.async group 0
    #pragma unroll
    for (int t = 0; t < 8; t++) {
        const int i = tid + t * 512;                 // 0..4095
        const int mat = i >> 11, rem = i & 2047, row = rem >> 3, c16 = rem & 7;
        const __nv_bfloat16* g = (mat ? Qlo_g : Qhi_g) + row * HD_ + c16 * 8;
        cp16(sb + (uint32_t)(mat * QSZ + row * QP) * 2 + c16 * 16, g);
    }

    auto prefetch = [&](int c) {
        const int stage = c & 1;
        const int k0 = c * 64;
        const uint32_t base = (uint32_t)(2 * QSZ + stage * 4 * CHE);
        #pragma unroll
        for (int t = 0; t < 4; t++) {
            const int i = tid + t * 512;             // 0..2047
            const int mat = i >> 9, rem = i & 511, row = rem >> 3, c16 = rem & 7;
            const __nv_bfloat16* g;
            if (mat == 0)      g = Khi_g + (size_t)(k0 + row) * HD_ + c16 * 8;
            else if (mat == 1) g = Klo_g + (size_t)(k0 + row) * HD_ + c16 * 8;
            else if (mat == 2) g = Vhi_g + (size_t)row * S_ + k0 + c16 * 8;
            else               g = Vlo_g + (size_t)row * S_ + k0 + c16 * 8;
            cp16(sb + (base + (uint32_t)(mat * CHE + row * QP)) * 2 + c16 * 16, g);
        }
        asm volatile("cp.async.commit_group;" ::: "memory");
    };

    prefetch(0);   // group 0 (includes Q)
    prefetch(1);   // group 1

    const int arow  = (lane & 7) + ((lane >> 3) & 1) * 8;
    const int akoff = ((lane >> 4) & 1) * 8;
    const int btile = lane >> 4;
    const int bk    = (lane >> 3) & 1;
    const int br    = lane & 7;
    const int r = lane >> 2;

    float out[8][4];
    #pragma unroll
    for (int nt = 0; nt < 8; nt++)
        #pragma unroll
        for (int j = 0; j < 4; j++) out[nt][j] = 0.f;
    float p[8][4];        // raw scores -> (in-place softmax) -> P of chunk c
    float m0 = -1e30f, m1 = -1e30f, l0 = 0.f, l1 = 0.f;

    const uint32_t mrow0 = ((uint32_t)b * S_ + q0 + wid * 16 + r) * (S_/32);

    // ---- in-place softmax on p (chunk cc): mask, max, ex2, l/m, out rescale
    auto softmax_chunk = [&](int cc) {
        const uint32_t widx = (uint32_t)(cc * 2);
        const uint2 mw0 = *(const uint2*)(g_mbits + mrow0 + widx);
        const uint2 mw1 = *(const uint2*)(g_mbits + mrow0 + 8 * (S_/32) + widx);
        #pragma unroll
        for (int nt = 0; nt < 8; nt++) {
            const int sh = ((nt * 8) & 31) + (lane & 3) * 2;
            const uint32_t w0 = (nt < 4) ? mw0.x : mw0.y;
            const uint32_t w1 = (nt < 4) ? mw1.x : mw1.y;
            if (!((w0 >> sh) & 1))       p[nt][0] = -1e9f;
            if (!((w0 >> (sh + 1)) & 1)) p[nt][1] = -1e9f;
            if (!((w1 >> sh) & 1))       p[nt][2] = -1e9f;
            if (!((w1 >> (sh + 1)) & 1)) p[nt][3] = -1e9f;
        }
        float mx0 = -1e30f, mx1 = -1e30f;
        #pragma unroll
        for (int nt = 0; nt < 8; nt++) {
            mx0 = fmaxf(mx0, fmaxf(p[nt][0], p[nt][1]));
            mx1 = fmaxf(mx1, fmaxf(p[nt][2], p[nt][3]));
        }
        mx0 = fmaxf(mx0, __shfl_xor_sync(0xffffffffu, mx0, 1));
        mx0 = fmaxf(mx0, __shfl_xor_sync(0xffffffffu, mx0, 2));
        mx1 = fmaxf(mx1, __shfl_xor_sync(0xffffffffu, mx1, 1));
        mx1 = fmaxf(mx1, __shfl_xor_sync(0xffffffffu, mx1, 2));
        const float mn0 = fmaxf(m0, mx0);
        const float mn1 = fmaxf(m1, mx1);
        const float a0 = ex2f(m0 - mn0);
        const float a1 = ex2f(m1 - mn1);
        m0 = mn0; m1 = mn1;
        float s0 = 0.f, s1 = 0.f;
        #pragma unroll
        for (int nt = 0; nt < 8; nt++) {
            p[nt][0] = ex2f(p[nt][0] - mn0); s0 += p[nt][0];
            p[nt][1] = ex2f(p[nt][1] - mn0); s0 += p[nt][1];
            p[nt][2] = ex2f(p[nt][2] - mn1); s1 += p[nt][2];
            p[nt][3] = ex2f(p[nt][3] - mn1); s1 += p[nt][3];
        }
        s0 += __shfl_xor_sync(0xffffffffu, s0, 1);
        s0 += __shfl_xor_sync(0xffffffffu, s0, 2);
        s1 += __shfl_xor_sync(0xffffffffu, s1, 1);
        s1 += __shfl_xor_sync(0xffffffffu, s1, 2);
        l0 = l0 * a0 + s0;
        l1 = l1 * a1 + s1;
        #pragma unroll
        for (int nt = 0; nt < 8; nt++) {
            out[nt][0] *= a0; out[nt][1] *= a0;
            out[nt][2] *= a1; out[nt][3] *= a1;
        }
    };

    // ---- QK into p from given stage base (byte addr) ----
    auto qk_chunk = [&](uint32_t kb) {
        #pragma unroll
        for (int nt = 0; nt < 8; nt++)
            #pragma unroll
            for (int j = 0; j < 4; j++) p[nt][j] = 0.f;
        #pragma unroll
        for (int ks = 0; ks < 4; ks++) {
            uint32_t qh[4], ql[4];
            const uint32_t qa =
                (uint32_t)((wid * 16 + arow) * QP + ks * 16 + akoff) * 2;
            ldm_x4(qh, sb + qa);
            ldm_x4(ql, sb + (uint32_t)QSZ * 2 + qa);
            #pragma unroll
            for (int half = 0; half < 2; half++) {
                uint32_t kh[4][2], kl[4][2];
                #pragma unroll
                for (int pp = 0; pp < 2; pp++) {
                    const int t0 = half * 4 + pp * 2;
                    const uint32_t ka = kb + (uint32_t)(
                        ((t0 + btile) * 8 + br) * QP + ks * 16 + bk * 8) * 2;
                    ldm_x4(&kh[pp*2][0], ka);
                    ldm_x4(&kl[pp*2][0], ka + (uint32_t)CHE * 2);
                }
                #pragma unroll
                for (int q = 0; q < 4; q++) mma_bf16(p[half*4+q], qh, kh[q]);
                #pragma unroll
                for (int q = 0; q < 4; q++) mma_bf16(p[half*4+q], qh, kl[q]);
                #pragma unroll
                for (int q = 0; q < 4; q++) mma_bf16(p[half*4+q], ql, kh[q]);
            }
        }
    };

    // ---- PV from given stage base, consuming P in p ----
    auto pv_chunk = [&](uint32_t kb) {
        #pragma unroll
        for (int j = 0; j < 4; j++) {
            uint32_t ah[4], al[4];
            split2(p[2*j][0],   p[2*j][1],   ah[0], al[0]);
            split2(p[2*j][2],   p[2*j][3],   ah[1], al[1]);
            split2(p[2*j+1][0], p[2*j+1][1], ah[2], al[2]);
            split2(p[2*j+1][2], p[2*j+1][3], ah[3], al[3]);
            #pragma unroll
            for (int half = 0; half < 2; half++) {
                uint32_t vh[4][2], vl[4][2];
                #pragma unroll
                for (int pp = 0; pp < 2; pp++) {
                    const int t0 = half * 4 + pp * 2;
                    const uint32_t va = kb + (uint32_t)(
                        2 * CHE + ((t0 + btile) * 8 + br) * QP + j * 16 + bk * 8) * 2;
                    ldm_x4(&vh[pp*2][0], va);
                    ldm_x4(&vl[pp*2][0], va + (uint32_t)CHE * 2);
                }
                #pragma unroll
                for (int q = 0; q < 4; q++) mma_bf16(out[half*4+q], ah, vh[q]);
                #pragma unroll
                for (int q = 0; q < 4; q++) mma_bf16(out[half*4+q], ah, vl[q]);
                #pragma unroll
                for (int q = 0; q < 4; q++) mma_bf16(out[half*4+q], al, vh[q]);
            }
        }
    };

    const uint32_t stage0 = sb + (uint32_t)(2 * QSZ) * 2;
    const uint32_t stage1 = sb + (uint32_t)(2 * QSZ + 4 * CHE) * 2;

    // ---- prologue: QK(0) + softmax(0) ----
    asm volatile("cp.async.wait_group 1;" ::: "memory");   // group 0 (Q + chunk0)
    __syncthreads();
    qk_chunk(stage0);
    softmax_chunk(0);

    // ---- pipelined main loop ----
    for (int c = 0; c < 31; c++) {
        const uint32_t kbP = (c & 1) ? stage1 : stage0;
        const uint32_t kbQ = (c & 1) ? stage0 : stage1;

        pv_chunk(kbP);                                      // PV(c)
        asm volatile("cp.async.wait_group 0;" ::: "memory"); // own group c+1 done
        __syncthreads();   // all threads' group c+1 visible; all PV(c) reads done
        qk_chunk(kbQ);                                      // QK(c+1)
        if (c < 30) prefetch(c + 2);                        // overwrites stage c&1
        softmax_chunk(c + 1);                               // scalar tail, drifts
    }

    // ---- final PV(31) (stage 31&1 = 1) ----
    pv_chunk(stage1);

    // ---- epilogue: normalize, split, store bf16 hi/lo into g_xhi/g_xlo ----
    const float i0 = 1.0f / l0;
    const float i1 = 1.0f / l1;
    const int qg = q0 + wid * 16 + r;
    #pragma unroll
    for (int nt = 0; nt < 8; nt++) {
        const int d = nt * 8 + (lane & 3) * 2;
        const size_t o0 = ((size_t)b * S_ + qg) * D_ + h * HD_ + d;
        const size_t o1 = o0 + 8 * D_;
        uint32_t hw, lw;
        split2(out[nt][0] * i0, out[nt][1] * i0, hw, lw);
        *(uint32_t*)&g_xhi[o0] = hw;
        *(uint32_t*)&g_xlo[o0] = lw;
        split2(out[nt][2] * i1, out[nt][3] * i1, hw, lw);
        *(uint32_t*)&g_xhi[o1] = hw;
        *(uint32_t*)&g_xlo[o1] = lw;
    }
}

// ---------------------------------------------------------------------------
extern "C" void kernel_launch(void* const* d_in, const int* in_sizes, int n_in,
                              void* d_out, int out_size)
{
    const float* x  = (const float*)d_in[0];
    const int*   Mm = (const int*)  d_in[1];
    const float* Wq = (const float*)d_in[2];
    const float* Wk = (const float*)d_in[3];
    const float* Wv = (const float*)d_in[4];
    const float* Wo = (const float*)d_in[5];
    const float* bo = (const float*)d_in[6];
    float* out = (float*)d_out;

    __nv_bfloat16 *xhiPtr = nullptr, *xloPtr = nullptr;
    cudaGetSymbolAddress((void**)&xhiPtr, g_xhi);
    cudaGetSymbolAddress((void**)&xloPtr, g_xlo);

    const int gemm_smem = 2 * 4 * TILE_ELT * 2;             // 81920 B
    cudaFuncSetAttribute(tgemm_kernel<0>,
                         cudaFuncAttributeMaxDynamicSharedMemorySize, gemm_smem);
    cudaFuncSetAttribute(tgemm_kernel<1>,
                         cudaFuncAttributeMaxDynamicSharedMemorySize, gemm_smem);
    const int attn_smem = (2 * QSZ + 8 * CHE) * 2;          // 147456 B
    cudaFuncSetAttribute(attn_tc,
                         cudaFuncAttributeMaxDynamicSharedMemorySize, attn_smem);

    // 1) split input x and all weights to hi/lo bf16
    split_x_kernel<<<NELEM/1024, 256>>>(x, xhiPtr, xloPtr);
    split_w_kernel<<<dim3((D_*D_)/1024, 4), 256>>>(Wq, Wk, Wv, Wo);
    // 2) QKV projections (HMMA); epilogue splits Q/K to bf16, V stays fp32
    tgemm_kernel<0><<<dim3(8, 32, 3), 256, gemm_smem>>>(xhiPtr, xloPtr, nullptr, nullptr);
    // 3) pack mask bits; transpose+split V
    packmask_kernel<<<(B_*S_)/8, 256>>>(Mm);
    vtrans_kernel<<<dim3(S_/64, B_*H_), 256>>>();
    // 4) pipelined tensor-core flash attention -> g_xhi/g_xlo [B,S,D]
    attn_tc<<<dim3(S_/QROWS, B_*H_), 512, attn_smem>>>();
    // 5) output projection + bias (HMMA)
    tgemm_kernel<1><<<dim3(8, 32, 1), 256, gemm_smem>>>(xhiPtr, xloPtr, bo, out);
}